// round 1
// baseline (speedup 1.0000x reference)
#include <cuda_runtime.h>
#include <cstddef>

// Problem constants
#define M_TOK   8192     // M*B token rows
#define D_MODEL 1024
#define FF_DIM  4096
#define NHEAD   16
#define DHEAD   64
#define SEQ     1024
#define BATCH   8

// ---------------- scratch (static device memory; no allocations allowed) ----------------
// floats:
//  xn     8388608
//  v      8388608
//  pool   8388608
//  x2     8388608
//  h      33554432
//  qs     131072
//  ks     131072
//  wqs    16384
//  wks    16384
//  bqs    16
//  bks    16
static const size_t OFF_XN   = 0;
static const size_t OFF_V    = 8388608;
static const size_t OFF_POOL = 16777216;
static const size_t OFF_X2   = 25165824;
static const size_t OFF_H    = 33554432;
static const size_t OFF_QS   = 67108864;
static const size_t OFF_KS   = 67239936;
static const size_t OFF_WQS  = 67371008;
static const size_t OFF_WKS  = 67387392;
static const size_t OFF_BQS  = 67403776;
static const size_t OFF_BKS  = 67403792;
static const size_t SCRATCH_FLOATS = 67403808;

__device__ float g_scratch[SCRATCH_FLOATS];

// ---------------- LayerNorm: one block per row (D=1024, 256 threads x float4) ----------------
__global__ void __launch_bounds__(256)
ln_kernel(const float* __restrict__ x, const float* __restrict__ g,
          const float* __restrict__ bta, float* __restrict__ y)
{
    const int row = blockIdx.x;
    const int tx  = threadIdx.x;
    const float4 v = ((const float4*)(x + (size_t)row * D_MODEL))[tx];

    float s  = v.x + v.y + v.z + v.w;
    float sq = v.x * v.x + v.y * v.y + v.z * v.z + v.w * v.w;
    #pragma unroll
    for (int o = 16; o; o >>= 1) {
        s  += __shfl_xor_sync(0xffffffffu, s,  o);
        sq += __shfl_xor_sync(0xffffffffu, sq, o);
    }
    __shared__ float ss[8], ssq[8];
    const int w = tx >> 5, l = tx & 31;
    if (l == 0) { ss[w] = s; ssq[w] = sq; }
    __syncthreads();
    s = 0.f; sq = 0.f;
    #pragma unroll
    for (int i = 0; i < 8; i++) { s += ss[i]; sq += ssq[i]; }

    const float mean = s * (1.f / D_MODEL);
    const float var  = sq * (1.f / D_MODEL) - mean * mean;
    const float rstd = rsqrtf(var + 1e-5f);

    const float4 gv = ((const float4*)g)[tx];
    const float4 bv = ((const float4*)bta)[tx];
    float4 o4;
    o4.x = (v.x - mean) * rstd * gv.x + bv.x;
    o4.y = (v.y - mean) * rstd * gv.y + bv.y;
    o4.z = (v.z - mean) * rstd * gv.z + bv.z;
    o4.w = (v.w - mean) * rstd * gv.w + bv.w;
    ((float4*)(y + (size_t)row * D_MODEL))[tx] = o4;
}

// ---------------- head-sum of wq/wk columns (rank-1 attention folding) ----------------
__global__ void headsum_kernel(const float* __restrict__ wq, const float* __restrict__ bq,
                               const float* __restrict__ wk, const float* __restrict__ bk,
                               float* __restrict__ wqs, float* __restrict__ wks,
                               float* __restrict__ bqs, float* __restrict__ bks)
{
    const int idx = blockIdx.x * blockDim.x + threadIdx.x;
    if (idx < D_MODEL * NHEAD) {
        const int d = idx >> 4, h = idx & 15;
        const float* pq = wq + (size_t)d * D_MODEL + h * DHEAD;
        const float* pk = wk + (size_t)d * D_MODEL + h * DHEAD;
        float sq = 0.f, sk = 0.f;
        #pragma unroll 8
        for (int i = 0; i < DHEAD; i++) { sq += pq[i]; sk += pk[i]; }
        wqs[idx] = sq; wks[idx] = sk;
    }
    if (idx < NHEAD) {
        float sq = 0.f, sk = 0.f;
        for (int i = 0; i < DHEAD; i++) {
            sq += bq[idx * DHEAD + i];
            sk += bk[idx * DHEAD + i];
        }
        bqs[idx] = sq; bks[idx] = sk;
    }
}

// ---------------- skinny GEMM: qs/ks = xn @ wqs/wks + b  (one warp per token row) ----------------
__global__ void __launch_bounds__(256)
qsks_kernel(const float* __restrict__ xn,
            const float* __restrict__ wqs, const float* __restrict__ bqs,
            const float* __restrict__ wks, const float* __restrict__ bks,
            float* __restrict__ qs, float* __restrict__ ks)
{
    const int gw   = (blockIdx.x * blockDim.x + threadIdx.x) >> 5;
    const int lane = threadIdx.x & 31;
    if (gw >= M_TOK) return;

    const float* xr = xn + (size_t)gw * D_MODEL;
    float aq[NHEAD], ak[NHEAD];
    #pragma unroll
    for (int hh = 0; hh < NHEAD; hh++) { aq[hh] = 0.f; ak[hh] = 0.f; }

    for (int d = lane; d < D_MODEL; d += 32) {
        const float xv = xr[d];
        const float* wq = wqs + d * NHEAD;
        const float* wk = wks + d * NHEAD;
        #pragma unroll
        for (int hh = 0; hh < NHEAD; hh++) {
            aq[hh] = fmaf(xv, wq[hh], aq[hh]);
            ak[hh] = fmaf(xv, wk[hh], ak[hh]);
        }
    }
    #pragma unroll
    for (int hh = 0; hh < NHEAD; hh++) {
        #pragma unroll
        for (int o = 16; o; o >>= 1) {
            aq[hh] += __shfl_xor_sync(0xffffffffu, aq[hh], o);
            ak[hh] += __shfl_xor_sync(0xffffffffu, ak[hh], o);
        }
    }
    if (lane == 0) {
        #pragma unroll
        for (int hh = 0; hh < NHEAD; hh++) {
            qs[(size_t)gw * NHEAD + hh] = aq[hh] + bqs[hh];
            ks[(size_t)gw * NHEAD + hh] = ak[hh] + bks[hh];
        }
    }
}

// ---------------- SGEMM 128x128x8, 256 threads, 8x8 per thread ----------------
// C[M_TOK, N] = A[M_TOK, K] @ W[K, N] + bias (+resid) (relu). All dims multiples of 128/8.
template<bool RELU, bool RESID>
__global__ void __launch_bounds__(256)
sgemm_kernel(const float* __restrict__ A, const float* __restrict__ W,
             const float* __restrict__ bias, const float* __restrict__ resid,
             float* __restrict__ C, int N, int K)
{
    __shared__ float As[8][128];
    __shared__ float Ws[8][128];

    const int tx   = threadIdx.x;
    const int brow = blockIdx.y << 7;
    const int bcol = blockIdx.x << 7;
    const int tm   = (tx >> 4) << 3;
    const int tn   = (tx & 15) << 3;

    float acc[8][8];
    #pragma unroll
    for (int i = 0; i < 8; i++)
        #pragma unroll
        for (int j = 0; j < 8; j++) acc[i][j] = 0.f;

    const int aRow = tx >> 1;
    const int aCol = (tx & 1) << 2;
    const int wRow = tx >> 5;
    const int wCol = (tx & 31) << 2;

    const float* Ap = A + (size_t)(brow + aRow) * K + aCol;
    const float* Wp = W + (size_t)wRow * N + bcol + wCol;

    for (int k0 = 0; k0 < K; k0 += 8) {
        const float4 a4 = *(const float4*)(Ap + k0);
        As[aCol + 0][aRow] = a4.x;
        As[aCol + 1][aRow] = a4.y;
        As[aCol + 2][aRow] = a4.z;
        As[aCol + 3][aRow] = a4.w;
        *(float4*)&Ws[wRow][wCol] = *(const float4*)(Wp + (size_t)k0 * N);
        __syncthreads();

        #pragma unroll
        for (int kk = 0; kk < 8; kk++) {
            float ra[8], rb[8];
            #pragma unroll
            for (int i = 0; i < 8; i++) ra[i] = As[kk][tm + i];
            #pragma unroll
            for (int j = 0; j < 8; j++) rb[j] = Ws[kk][tn + j];
            #pragma unroll
            for (int i = 0; i < 8; i++)
                #pragma unroll
                for (int j = 0; j < 8; j++)
                    acc[i][j] = fmaf(ra[i], rb[j], acc[i][j]);
        }
        __syncthreads();
    }

    #pragma unroll
    for (int i = 0; i < 8; i++) {
        const size_t r = (size_t)(brow + tm + i);
        #pragma unroll
        for (int j = 0; j < 8; j += 4) {
            const int c = bcol + tn + j;
            const float4 bv = *(const float4*)(bias + c);
            float4 o;
            o.x = acc[i][j + 0] + bv.x;
            o.y = acc[i][j + 1] + bv.y;
            o.z = acc[i][j + 2] + bv.z;
            o.w = acc[i][j + 3] + bv.w;
            if (RESID) {
                const float4 rv = *(const float4*)(resid + r * N + c);
                o.x += rv.x; o.y += rv.y; o.z += rv.z; o.w += rv.w;
            }
            if (RELU) {
                o.x = fmaxf(o.x, 0.f); o.y = fmaxf(o.y, 0.f);
                o.z = fmaxf(o.z, 0.f); o.w = fmaxf(o.w, 0.f);
            }
            *(float4*)(C + r * N + c) = o;
        }
    }
}

// ---------------- attention: rank-1 scores + online softmax + P@V ----------------
// grid: (SEQ/64, BATCH*NHEAD). block 256. Each block: 64 queries of one (b,h).
__global__ void __launch_bounds__(256)
attn_kernel(const float* __restrict__ qs, const float* __restrict__ ks,
            const float* __restrict__ v, const unsigned char* __restrict__ mask,
            float* __restrict__ o)
{
    __shared__ float Vs[64][68];
    __shared__ float Ps[64][68];
    __shared__ float kss[64];
    __shared__ float qss[64];
    __shared__ unsigned char msk[64];

    const int tx = threadIdx.x;
    const int bh = blockIdx.y;
    const int b  = bh >> 4;
    const int h  = bh & 15;
    const int m0 = blockIdx.x << 6;

    const int row = tx >> 2;
    const int qd  = tx & 3;
    const int c0  = qd << 4;

    if (tx < 64)
        qss[tx] = qs[((size_t)(m0 + tx) * BATCH + b) * NHEAD + h];

    float m_run = -1e30f, l_run = 0.f;
    float acc[16];
    #pragma unroll
    for (int j = 0; j < 16; j++) acc[j] = 0.f;

    for (int n0 = 0; n0 < SEQ; n0 += 64) {
        __syncthreads();   // previous Ps/Vs fully consumed
        if (tx < 64) {
            kss[tx] = ks[((size_t)(n0 + tx) * BATCH + b) * NHEAD + h];
            msk[tx] = mask[(size_t)(n0 + tx) * BATCH + b];
        }
        #pragma unroll
        for (int t = 0; t < 4; t++) {
            const int idx = tx + (t << 8);
            const int n   = idx >> 4;
            const int j4  = (idx & 15) << 2;
            *(float4*)&Vs[n][j4] =
                *(const float4*)(v + ((size_t)(n0 + n) * BATCH + b) * D_MODEL + h * DHEAD + j4);
        }
        __syncthreads();

        const float qv = qss[row];
        float s[16];
        float tmax = -1e30f;
        #pragma unroll
        for (int cc = 0; cc < 16; cc++) {
            const float sv = msk[c0 + cc] ? -1000.0f : qv * kss[c0 + cc];
            s[cc] = sv;
            tmax = fmaxf(tmax, sv);
        }
        tmax = fmaxf(tmax, __shfl_xor_sync(0xffffffffu, tmax, 1));
        tmax = fmaxf(tmax, __shfl_xor_sync(0xffffffffu, tmax, 2));
        const float m_new = fmaxf(m_run, tmax);

        float psum = 0.f;
        #pragma unroll
        for (int cc = 0; cc < 16; cc++) {
            const float p = __expf(s[cc] - m_new);
            Ps[row][c0 + cc] = p;
            psum += p;
        }
        psum += __shfl_xor_sync(0xffffffffu, psum, 1);
        psum += __shfl_xor_sync(0xffffffffu, psum, 2);

        const float scale = __expf(m_run - m_new);
        l_run = l_run * scale + psum;
        m_run = m_new;
        #pragma unroll
        for (int j = 0; j < 16; j++) acc[j] *= scale;
        __syncthreads();   // Ps complete

        #pragma unroll 4
        for (int n = 0; n < 64; n++) {
            const float pv = Ps[row][n];
            const float4* vrow = (const float4*)&Vs[n][c0];
            const float4 v0 = vrow[0], v1 = vrow[1], v2 = vrow[2], v3 = vrow[3];
            acc[0]  = fmaf(pv, v0.x, acc[0]);  acc[1]  = fmaf(pv, v0.y, acc[1]);
            acc[2]  = fmaf(pv, v0.z, acc[2]);  acc[3]  = fmaf(pv, v0.w, acc[3]);
            acc[4]  = fmaf(pv, v1.x, acc[4]);  acc[5]  = fmaf(pv, v1.y, acc[5]);
            acc[6]  = fmaf(pv, v1.z, acc[6]);  acc[7]  = fmaf(pv, v1.w, acc[7]);
            acc[8]  = fmaf(pv, v2.x, acc[8]);  acc[9]  = fmaf(pv, v2.y, acc[9]);
            acc[10] = fmaf(pv, v2.z, acc[10]); acc[11] = fmaf(pv, v2.w, acc[11]);
            acc[12] = fmaf(pv, v3.x, acc[12]); acc[13] = fmaf(pv, v3.y, acc[13]);
            acc[14] = fmaf(pv, v3.z, acc[14]); acc[15] = fmaf(pv, v3.w, acc[15]);
        }
    }

    const float inv = 1.f / l_run;
    const size_t r = (size_t)(m0 + row) * BATCH + b;
    #pragma unroll
    for (int j = 0; j < 16; j += 4) {
        float4 ov;
        ov.x = acc[j + 0] * inv; ov.y = acc[j + 1] * inv;
        ov.z = acc[j + 2] * inv; ov.w = acc[j + 3] * inv;
        *(float4*)(o + r * D_MODEL + h * DHEAD + c0 + j) = ov;
    }
}

// ---------------- launcher ----------------
extern "C" void kernel_launch(void* const* d_in, const int* in_sizes, int n_in,
                              void* d_out, int out_size)
{
    const float* x     = (const float*)d_in[0];
    const unsigned char* mask = (const unsigned char*)d_in[1];
    const float* ln1_g = (const float*)d_in[2];
    const float* ln1_b = (const float*)d_in[3];
    const float* wq    = (const float*)d_in[4];
    const float* bq    = (const float*)d_in[5];
    const float* wk    = (const float*)d_in[6];
    const float* bk    = (const float*)d_in[7];
    const float* wv    = (const float*)d_in[8];
    const float* bv    = (const float*)d_in[9];
    const float* wo    = (const float*)d_in[10];
    const float* bo    = (const float*)d_in[11];
    const float* ln2_g = (const float*)d_in[12];
    const float* ln2_b = (const float*)d_in[13];
    const float* w1    = (const float*)d_in[14];
    const float* b1    = (const float*)d_in[15];
    const float* w2    = (const float*)d_in[16];
    const float* b2    = (const float*)d_in[17];
    float* out = (float*)d_out;

    float* scratch = nullptr;
    cudaGetSymbolAddress((void**)&scratch, g_scratch);
    float* xn   = scratch + OFF_XN;
    float* vbuf = scratch + OFF_V;
    float* pool = scratch + OFF_POOL;
    float* x2   = scratch + OFF_X2;
    float* hbuf = scratch + OFF_H;
    float* qsb  = scratch + OFF_QS;
    float* ksb  = scratch + OFF_KS;
    float* wqs  = scratch + OFF_WQS;
    float* wks  = scratch + OFF_WKS;
    float* bqs  = scratch + OFF_BQS;
    float* bks  = scratch + OFF_BKS;

    // 1. xn = LN1(x)
    ln_kernel<<<M_TOK, 256>>>(x, ln1_g, ln1_b, xn);
    // 2. fold head-sums of wq/wk (rank-1 attention)
    headsum_kernel<<<64, 256>>>(wq, bq, wk, bk, wqs, wks, bqs, bks);
    // 3. v = xn @ wv + bv
    sgemm_kernel<false, false><<<dim3(D_MODEL / 128, M_TOK / 128), 256>>>(
        xn, wv, bv, nullptr, vbuf, D_MODEL, D_MODEL);
    // 4. qs/ks = xn @ wqs/wks + b (skinny)
    qsks_kernel<<<M_TOK / 8, 256>>>(xn, wqs, bqs, wks, bks, qsb, ksb);
    // 5. pooled = softmax(qs ⊗ ks, masked) @ v
    attn_kernel<<<dim3(SEQ / 64, BATCH * NHEAD), 256>>>(qsb, ksb, vbuf, mask, pool);
    // 6. x2 = pooled @ wo + bo + x
    sgemm_kernel<false, true><<<dim3(D_MODEL / 128, M_TOK / 128), 256>>>(
        pool, wo, bo, x, x2, D_MODEL, D_MODEL);
    // 7. xn = LN2(x2)
    ln_kernel<<<M_TOK, 256>>>(x2, ln2_g, ln2_b, xn);
    // 8. h = relu(xn @ w1 + b1)
    sgemm_kernel<true, false><<<dim3(FF_DIM / 128, M_TOK / 128), 256>>>(
        xn, w1, b1, nullptr, hbuf, FF_DIM, D_MODEL);
    // 9. out = h @ w2 + b2 + x2
    sgemm_kernel<false, true><<<dim3(D_MODEL / 128, M_TOK / 128), 256>>>(
        hbuf, w2, b2, x2, out, D_MODEL, FF_DIM);
}